// round 6
// baseline (speedup 1.0000x reference)
#include <cuda_runtime.h>
#include <cuda_bf16.h>

// MulticlassDice fused, ballot+popc histogram version.
// dice[n][c] = (2*inter + 1e-5) / (cnt_in + cnt_tg + 1e-5)
// Output: [total, dice[0..7]] (verified rel_err=0).

#define NCLS 8
#define PIX (512 * 512)
#define MAXN 8
#define GX 64             // blocks per sample
#define NSLOT (3 * NCLS)  // 24: [in|tg|inter] x class

__device__ int g_partial[MAXN][GX][NSLOT];
__device__ unsigned int g_done;  // zero-init; last block resets to 0

__global__ __launch_bounds__(256) void k_dice_fused(const int* __restrict__ inB,
                                                    const int* __restrict__ tgB,
                                                    const float* __restrict__ w,
                                                    float* __restrict__ out,
                                                    int out_size, int N) {
    const int n = blockIdx.y;
    const int tid = threadIdx.x;

    // ---- per-block dtype detect (odd 32-bit words all zero => int64) ----
    __shared__ int s_is64;
    if (tid < 32) {
        int nz = 0;
#pragma unroll
        for (int i = 0; i < 8; i++) nz |= __ldg(&inB[2 * (tid + 32 * i) + 1]);
        unsigned mask = __ballot_sync(0xffffffffu, nz != 0);
        if (tid == 0) s_is64 = (mask == 0u) ? 1 : 0;
    }
    __syncthreads();
    const bool is64 = (s_is64 != 0);

    // Warp-uniform counters (ballot totals; every lane holds the same value).
    int cin[NCLS], ctg[NCLS], cxx[NCLS];
#pragma unroll
    for (int c = 0; c < NCLS; c++) { cin[c] = 0; ctg[c] = 0; cxx[c] = 0; }

    const int stride = GX * 256;
    const int t0 = blockIdx.x * 256 + tid;
    const unsigned FULL = 0xffffffffu;

    if (is64) {
        // 2 pixels per int4 (low halves at .x/.z). PIX/2 = 8*stride exactly.
        const int4* a = (const int4*)inB + (size_t)n * (PIX / 2);
        const int4* b = (const int4*)tgB + (size_t)n * (PIX / 2);
        for (int i = t0; i < PIX / 2; i += 2 * stride) {
            int4 va0 = a[i],          vb0 = b[i];
            int4 va1 = a[i + stride], vb1 = b[i + stride];
#pragma unroll
            for (int c = 0; c < NCLS; c++) {
                unsigned ax0 = __ballot_sync(FULL, va0.x == c);
                unsigned az0 = __ballot_sync(FULL, va0.z == c);
                unsigned bx0 = __ballot_sync(FULL, vb0.x == c);
                unsigned bz0 = __ballot_sync(FULL, vb0.z == c);
                unsigned ax1 = __ballot_sync(FULL, va1.x == c);
                unsigned az1 = __ballot_sync(FULL, va1.z == c);
                unsigned bx1 = __ballot_sync(FULL, vb1.x == c);
                unsigned bz1 = __ballot_sync(FULL, vb1.z == c);
                cin[c] += __popc(ax0) + __popc(az0) + __popc(ax1) + __popc(az1);
                ctg[c] += __popc(bx0) + __popc(bz0) + __popc(bx1) + __popc(bz1);
                cxx[c] += __popc(ax0 & bx0) + __popc(az0 & bz0) +
                          __popc(ax1 & bx1) + __popc(az1 & bz1);
            }
        }
    } else {
        // 4 pixels per int4. PIX/4 = 4*stride exactly.
        const int4* a = (const int4*)inB + (size_t)n * (PIX / 4);
        const int4* b = (const int4*)tgB + (size_t)n * (PIX / 4);
        for (int i = t0; i < PIX / 4; i += 2 * stride) {
            int4 va0 = a[i],          vb0 = b[i];
            int4 va1 = a[i + stride], vb1 = b[i + stride];
#pragma unroll
            for (int c = 0; c < NCLS; c++) {
                unsigned ax0 = __ballot_sync(FULL, va0.x == c);
                unsigned ay0 = __ballot_sync(FULL, va0.y == c);
                unsigned az0 = __ballot_sync(FULL, va0.z == c);
                unsigned aw0 = __ballot_sync(FULL, va0.w == c);
                unsigned bx0 = __ballot_sync(FULL, vb0.x == c);
                unsigned by0 = __ballot_sync(FULL, vb0.y == c);
                unsigned bz0 = __ballot_sync(FULL, vb0.z == c);
                unsigned bw0 = __ballot_sync(FULL, vb0.w == c);
                unsigned ax1 = __ballot_sync(FULL, va1.x == c);
                unsigned ay1 = __ballot_sync(FULL, va1.y == c);
                unsigned az1 = __ballot_sync(FULL, va1.z == c);
                unsigned aw1 = __ballot_sync(FULL, va1.w == c);
                unsigned bx1 = __ballot_sync(FULL, vb1.x == c);
                unsigned by1 = __ballot_sync(FULL, vb1.y == c);
                unsigned bz1 = __ballot_sync(FULL, vb1.z == c);
                unsigned bw1 = __ballot_sync(FULL, vb1.w == c);
                cin[c] += __popc(ax0) + __popc(ay0) + __popc(az0) + __popc(aw0) +
                          __popc(ax1) + __popc(ay1) + __popc(az1) + __popc(aw1);
                ctg[c] += __popc(bx0) + __popc(by0) + __popc(bz0) + __popc(bw0) +
                          __popc(bx1) + __popc(by1) + __popc(bz1) + __popc(bw1);
                cxx[c] += __popc(ax0 & bx0) + __popc(ay0 & by0) +
                          __popc(az0 & bz0) + __popc(aw0 & bw0) +
                          __popc(ax1 & bx1) + __popc(ay1 & by1) +
                          __popc(az1 & bz1) + __popc(aw1 & bw1);
            }
        }
    }

    // ---- block reduce: counters are warp totals; lane 0 publishes ----
    __shared__ int s[NSLOT];
    if (tid < NSLOT) s[tid] = 0;
    __syncthreads();
    if ((tid & 31) == 0) {
#pragma unroll
        for (int c = 0; c < NCLS; c++) {
            atomicAdd(&s[0 * NCLS + c], cin[c]);
            atomicAdd(&s[1 * NCLS + c], ctg[c]);
            atomicAdd(&s[2 * NCLS + c], cxx[c]);
        }
    }
    __syncthreads();
    if (tid < NSLOT) g_partial[n][blockIdx.x][tid] = s[tid];

    // ---- last-block-done epilogue ----
    __threadfence();
    __shared__ bool s_last;
    if (tid == 0) {
        unsigned int prev = atomicAdd(&g_done, 1u);
        s_last = (prev == (unsigned int)(GX * N - 1));
    }
    __syncthreads();
    if (!s_last) return;

    __threadfence();  // acquire

    __shared__ int cnt_s[MAXN][NSLOT];
    for (int p = tid; p < N * NSLOT; p += 256) {
        int nn = p / NSLOT, slot = p % NSLOT;
        int acc = 0;
#pragma unroll 8
        for (int b = 0; b < GX; b++) acc += g_partial[nn][b][slot];
        cnt_s[nn][slot] = acc;
    }
    __syncthreads();

    __shared__ float dice[MAXN][NCLS];
    __shared__ float mean_c[NCLS];
    __shared__ float total_s;
    if (tid < N * NCLS) {
        int nn = tid / NCLS, c = tid % NCLS;
        float inter = (float)cnt_s[nn][2 * NCLS + c];
        float sums = (float)(cnt_s[nn][0 * NCLS + c] + cnt_s[nn][1 * NCLS + c]);
        dice[nn][c] = (2.0f * inter + 1e-5f) / (sums + 1e-5f);
    }
    __syncthreads();
    if (tid < NCLS) {
        float m = 0.0f;
        for (int i = 0; i < N; i++) m += dice[i][tid];
        mean_c[tid] = m / (float)N;
    }
    __syncthreads();
    if (tid == 0) {
        float t = 0.0f;
#pragma unroll
        for (int c = 0; c < NCLS; c++) t += w[c] * mean_c[c];
        total_s = t;
    }
    __syncthreads();

    for (int i = tid; i < out_size; i += 256) {
        float v;
        if (out_size >= NCLS + 1) {
            v = (i == 0) ? total_s : (i <= NCLS ? mean_c[i - 1] : 0.0f);
        } else if (out_size == NCLS) {
            v = mean_c[i];
        } else {
            v = (i == 0) ? total_s : (i - 1 < NCLS ? mean_c[i - 1] : 0.0f);
        }
        out[i] = v;
    }

    __threadfence();
    __syncthreads();
    if (tid == 0) g_done = 0u;  // replay-safe reset
}

extern "C" void kernel_launch(void* const* d_in, const int* in_sizes, int n_in,
                              void* d_out, int out_size) {
    const int* inB = (const int*)d_in[0];
    const int* tgB = (const int*)d_in[1];
    const float* w = (const float*)d_in[2];
    float* out = (float*)d_out;

    int N = in_sizes[0] / PIX;
    if (N < 1) N = 1;
    if (N > MAXN) N = MAXN;

    dim3 grid(GX, N);
    k_dice_fused<<<grid, 256>>>(inB, tgB, w, out, out_size, N);
}

// round 7
// speedup vs baseline: 2.0756x; 2.0756x over previous
#include <cuda_runtime.h>
#include <cuda_bf16.h>

// MulticlassDice fused, nibble-packed histogram version.
// Values in [0,8) => 8 classes fit one 32-bit reg as 4-bit nibbles.
// dice[n][c] = (2*inter + 1e-5) / (cnt_in + cnt_tg + 1e-5)
// Output: [total, dice[0..7]] (verified rel_err=0 in R3/R5/R6).

#define NCLS 8
#define PIX (512 * 512)
#define MAXN 8
#define GX 74             // 74 * 8 = 592 blocks = 4/SM on 148 SMs, one wave
#define NSLOT (3 * NCLS)  // 24: [in|tg|inter] x class

__device__ int g_cnt[MAXN][NSLOT];  // zero-init; last block re-zeros each launch
__device__ unsigned int g_done;     // zero-init; last block resets

// Accumulate one pixel pair into nibble-packed histograms.
__device__ __forceinline__ void acc_px(int a, int b, unsigned& hin, unsigned& htg,
                                       unsigned& hxx) {
    unsigned sa = 1u << (4 * a);
    unsigned sb = 1u << (4 * b);
    hin += sa;
    htg += sb;
    if (a == b) hxx += sa;  // intersection reuses sa
}

// Drain nibbles (cap 16) into byte-packed (cap 256).
// beven bytes = classes 0,2,4,6 ; bodd bytes = classes 1,3,5,7.
__device__ __forceinline__ void drain1(unsigned& h, unsigned& be, unsigned& bo) {
    be += h & 0x0F0F0F0Fu;
    bo += (h >> 4) & 0x0F0F0F0Fu;
    h = 0u;
}

__global__ __launch_bounds__(256) void k_dice_fused(const int* __restrict__ inB,
                                                    const int* __restrict__ tgB,
                                                    const float* __restrict__ w,
                                                    float* __restrict__ out,
                                                    int out_size, int N) {
    const int n = blockIdx.y;
    const int tid = threadIdx.x;
    const unsigned FULL = 0xffffffffu;

    // ---- per-block dtype detect (odd 32-bit words all zero => int64) ----
    __shared__ int s_is64;
    if (tid < 32) {
        int nz = 0;
#pragma unroll
        for (int i = 0; i < 8; i++) nz |= __ldg(&inB[2 * (tid + 32 * i) + 1]);
        unsigned mask = __ballot_sync(FULL, nz != 0);
        if (tid == 0) s_is64 = (mask == 0u) ? 1 : 0;
    }
    __syncthreads();
    const bool is64 = (s_is64 != 0);

    unsigned hin = 0, htg = 0, hxx = 0;               // nibble-packed
    unsigned be_in = 0, bo_in = 0, be_tg = 0, bo_tg = 0, be_xx = 0, bo_xx = 0;

    const int stride = GX * 256;
    const int t0 = blockIdx.x * 256 + tid;

    if (is64) {
        // 2 px per int4 (low halves .x/.z); <=14 iters/thread; drain every 7 (14<16).
        const int4* a = (const int4*)inB + (size_t)n * (PIX / 2);
        const int4* b = (const int4*)tgB + (size_t)n * (PIX / 2);
        int it = 0;
        for (int i = t0; i < PIX / 2; i += stride) {
            int4 va = a[i], vb = b[i];
            acc_px(va.x, vb.x, hin, htg, hxx);
            acc_px(va.z, vb.z, hin, htg, hxx);
            if (++it == 7) {
                drain1(hin, be_in, bo_in);
                drain1(htg, be_tg, bo_tg);
                drain1(hxx, be_xx, bo_xx);
                it = 0;
            }
        }
    } else {
        // 4 px per int4; <=4 iters/thread; drain every 3 (12<16).
        const int4* a = (const int4*)inB + (size_t)n * (PIX / 4);
        const int4* b = (const int4*)tgB + (size_t)n * (PIX / 4);
        int it = 0;
        for (int i = t0; i < PIX / 4; i += stride) {
            int4 va = a[i], vb = b[i];
            acc_px(va.x, vb.x, hin, htg, hxx);
            acc_px(va.y, vb.y, hin, htg, hxx);
            acc_px(va.z, vb.z, hin, htg, hxx);
            acc_px(va.w, vb.w, hin, htg, hxx);
            if (++it == 3) {
                drain1(hin, be_in, bo_in);
                drain1(htg, be_tg, bo_tg);
                drain1(hxx, be_xx, bo_xx);
                it = 0;
            }
        }
    }
    drain1(hin, be_in, bo_in);
    drain1(htg, be_tg, bo_tg);
    drain1(hxx, be_xx, bo_xx);

    // ---- extract 24 per-thread counters, warp REDUX, smem, global atomics ----
    int vals[NSLOT];
#pragma unroll
    for (int c = 0; c < NCLS; c++) {
        unsigned sh = 8u * (unsigned)(c >> 1);
        vals[0 * NCLS + c] = (int)((((c & 1) ? bo_in : be_in) >> sh) & 0xFFu);
        vals[1 * NCLS + c] = (int)((((c & 1) ? bo_tg : be_tg) >> sh) & 0xFFu);
        vals[2 * NCLS + c] = (int)((((c & 1) ? bo_xx : be_xx) >> sh) & 0xFFu);
    }
#pragma unroll
    for (int s = 0; s < NSLOT; s++) vals[s] = __reduce_add_sync(FULL, vals[s]);

    __shared__ int s_cnt[NSLOT];
    if (tid < NSLOT) s_cnt[tid] = 0;
    __syncthreads();
    if ((tid & 31) == 0) {
#pragma unroll
        for (int s = 0; s < NSLOT; s++) atomicAdd(&s_cnt[s], vals[s]);
    }
    __syncthreads();
    if (tid < NSLOT) atomicAdd(&g_cnt[n][tid], s_cnt[tid]);

    // ---- last-block-done epilogue ----
    __threadfence();
    __shared__ bool s_last;
    if (tid == 0) {
        unsigned int prev = atomicAdd(&g_done, 1u);
        s_last = (prev == (unsigned int)(GX * N - 1));
    }
    __syncthreads();
    if (!s_last) return;

    __threadfence();  // acquire: all g_cnt updates visible

    __shared__ float dice[MAXN][NCLS];
    __shared__ float mean_c[NCLS];
    __shared__ float total_s;
    if (tid < N * NCLS) {
        int nn = tid / NCLS, c = tid % NCLS;
        float inter = (float)g_cnt[nn][2 * NCLS + c];
        float sums = (float)(g_cnt[nn][0 * NCLS + c] + g_cnt[nn][1 * NCLS + c]);
        dice[nn][c] = (2.0f * inter + 1e-5f) / (sums + 1e-5f);
    }
    __syncthreads();
    if (tid < NCLS) {
        float m = 0.0f;
        for (int i = 0; i < N; i++) m += dice[i][tid];
        mean_c[tid] = m / (float)N;
    }
    __syncthreads();
    if (tid == 0) {
        float t = 0.0f;
#pragma unroll
        for (int c = 0; c < NCLS; c++) t += w[c] * mean_c[c];
        total_s = t;
    }
    __syncthreads();

    for (int i = tid; i < out_size; i += 256) {
        float v;
        if (out_size >= NCLS + 1) {
            v = (i == 0) ? total_s : (i <= NCLS ? mean_c[i - 1] : 0.0f);
        } else if (out_size == NCLS) {
            v = mean_c[i];
        } else {
            v = (i == 0) ? total_s : (i - 1 < NCLS ? mean_c[i - 1] : 0.0f);
        }
        out[i] = v;
    }

    // ---- reset state for next graph replay ----
    __syncthreads();
    if (tid < MAXN * NSLOT) ((int*)g_cnt)[tid] = 0;
    __threadfence();
    __syncthreads();
    if (tid == 0) g_done = 0u;
}

extern "C" void kernel_launch(void* const* d_in, const int* in_sizes, int n_in,
                              void* d_out, int out_size) {
    const int* inB = (const int*)d_in[0];
    const int* tgB = (const int*)d_in[1];
    const float* w = (const float*)d_in[2];
    float* out = (float*)d_out;

    int N = in_sizes[0] / PIX;
    if (N < 1) N = 1;
    if (N > MAXN) N = MAXN;

    dim3 grid(GX, N);
    k_dice_fused<<<grid, 256>>>(inB, tgB, w, out, out_size, N);
}

// round 8
// speedup vs baseline: 2.5500x; 1.2286x over previous
#include <cuda_runtime.h>
#include <cuda_bf16.h>

// MulticlassDice fused, nibble-packed histograms, latency-optimized.
// Values in [0,8): 8 classes fit one 32-bit reg as 4-bit nibbles.
// dice[n][c] = (2*inter + 1e-5) / (cnt_in + cnt_tg + 1e-5)
// Output: [total, dice[0..7]] (verified rel_err=0 in R3/R5/R6/R7).

#define NCLS 8
#define PIX (512 * 512)
#define MAXN 8
#define GX 74             // 74 * 8 = 592 blocks = exactly 4/SM on 148 SMs
#define NSLOT (3 * NCLS)  // 24
#define W32 (PIX / 4)     // 65536 int4-words per sample (int32 path)
#define W64 (PIX / 2)     // 131072 int4-words per sample (int64 path)
#define CH32 ((W32 + GX - 1) / GX)  // 886
#define CH64 ((W64 + GX - 1) / GX)  // 1772

__device__ int g_cnt[MAXN][NSLOT];  // zero-init; last block re-zeros
__device__ unsigned int g_done;     // zero-init; last block resets

__device__ __forceinline__ void acc_px(int a, int b, unsigned& hin, unsigned& htg,
                                       unsigned& hxx) {
    unsigned sa = 1u << (4 * a);
    unsigned sb = 1u << (4 * b);
    hin += sa;
    htg += sb;
    if (a == b) hxx += sa;
}

__device__ __forceinline__ void acc4(const int4& va, const int4& vb, unsigned& hin,
                                     unsigned& htg, unsigned& hxx) {
    acc_px(va.x, vb.x, hin, htg, hxx);
    acc_px(va.y, vb.y, hin, htg, hxx);
    acc_px(va.z, vb.z, hin, htg, hxx);
    acc_px(va.w, vb.w, hin, htg, hxx);
}

// nibbles (cap 16) -> byte-packed (cap 256)
__device__ __forceinline__ void drain1(unsigned& h, unsigned& be, unsigned& bo) {
    be += h & 0x0F0F0F0Fu;
    bo += (h >> 4) & 0x0F0F0F0Fu;
    h = 0u;
}

__global__ __launch_bounds__(256, 4) void k_dice_fused(const int* __restrict__ inB,
                                                       const int* __restrict__ tgB,
                                                       const float* __restrict__ w,
                                                       float* __restrict__ out,
                                                       int out_size, int N) {
    const int n = blockIdx.y;
    const int tid = threadIdx.x;
    const int lid = tid & 31;
    const int wid = tid >> 5;
    const unsigned FULL = 0xffffffffu;

    // ---- barrier-free dtype detect: every warp ballots the same 32 odd words ----
    unsigned dmask = __ballot_sync(FULL, __ldg(&inB[2 * lid + 1]) != 0);
    const bool is64 = (dmask == 0u);

    unsigned hin = 0, htg = 0, hxx = 0;
    unsigned be_in = 0, bo_in = 0, be_tg = 0, bo_tg = 0, be_xx = 0, bo_xx = 0;

    if (!is64) {
        // int32: contiguous chunk of CH32 words, 4 predicated phases, loads front-batched
        const int4* a = (const int4*)inB + (size_t)n * W32;
        const int4* b = (const int4*)tgB + (size_t)n * W32;
        const int start = blockIdx.x * CH32;
        const int end = min(start + CH32, W32);
        const int i0 = start + tid, i1 = i0 + 256, i2 = i0 + 512, i3 = i0 + 768;
        const bool v0 = i0 < end, v1 = i1 < end, v2 = i2 < end, v3 = i3 < end;
        int4 a0, a1, a2, a3, b0, b1, b2, b3;
        if (v0) { a0 = a[i0]; b0 = b[i0]; }
        if (v1) { a1 = a[i1]; b1 = b[i1]; }
        if (v2) { a2 = a[i2]; b2 = b[i2]; }
        if (v3) { a3 = a[i3]; b3 = b[i3]; }
        if (v0) acc4(a0, b0, hin, htg, hxx);
        if (v1) acc4(a1, b1, hin, htg, hxx);
        if (v2) acc4(a2, b2, hin, htg, hxx);  // <=12 per nibble
        drain1(hin, be_in, bo_in);
        drain1(htg, be_tg, bo_tg);
        drain1(hxx, be_xx, bo_xx);
        if (v3) acc4(a3, b3, hin, htg, hxx);  // <=4 per nibble
    } else {
        // int64: 2 px per int4 (low halves .x/.z); <=7 iters => <=14 per nibble
        const int4* a = (const int4*)inB + (size_t)n * W64;
        const int4* b = (const int4*)tgB + (size_t)n * W64;
        const int start = blockIdx.x * CH64;
        const int end = min(start + CH64, W64);
        for (int i = start + tid; i < end; i += 256) {
            int4 va = a[i], vb = b[i];
            acc_px(va.x, vb.x, hin, htg, hxx);
            acc_px(va.z, vb.z, hin, htg, hxx);
        }
    }
    drain1(hin, be_in, bo_in);
    drain1(htg, be_tg, bo_tg);
    drain1(hxx, be_xx, bo_xx);

    // ---- pack byte counters into 16-bit pairs, 12 REDUX per warp ----
    // per type: r0 = (c0,c4), r1 = (c2,c6), r2 = (c1,c5), r3 = (c3,c7)
    const unsigned M = 0x00FF00FFu;
    unsigned r[12];
    r[0] = be_in & M;  r[1] = (be_in >> 8) & M;
    r[2] = bo_in & M;  r[3] = (bo_in >> 8) & M;
    r[4] = be_tg & M;  r[5] = (be_tg >> 8) & M;
    r[6] = bo_tg & M;  r[7] = (bo_tg >> 8) & M;
    r[8] = be_xx & M;  r[9] = (be_xx >> 8) & M;
    r[10] = bo_xx & M; r[11] = (bo_xx >> 8) & M;
#pragma unroll
    for (int j = 0; j < 12; j++) r[j] = __reduce_add_sync(FULL, r[j]);

    __shared__ unsigned s_ph[8][12];
    if (lid == 0) {
#pragma unroll
        for (int j = 0; j < 12; j++) s_ph[wid][j] = r[j];
    }
    __syncthreads();

    // 24 threads gather across the 8 warps and publish to global counters
    if (tid < NSLOT) {
        int t = tid / NCLS, c = tid % NCLS;
        int j = t * 4 + (c & 1) * 2 + ((c >> 1) & 1);
        int h = (c >> 2) * 16;
        int acc = 0;
#pragma unroll
        for (int ww = 0; ww < 8; ww++) acc += (int)((s_ph[ww][j] >> h) & 0xFFFFu);
        atomicAdd(&g_cnt[n][tid], acc);
    }
    __syncthreads();

    // ---- last-block-done via acq_rel atomic (no threadfence) ----
    __shared__ bool s_last;
    if (tid == 0) {
        unsigned int* gp = &g_done;
        unsigned int prev;
        asm volatile("atom.add.acq_rel.gpu.u32 %0, [%1], %2;"
                     : "=r"(prev)
                     : "l"(gp), "r"(1u)
                     : "memory");
        s_last = (prev == (unsigned int)(GX * N - 1));
    }
    __syncthreads();
    if (!s_last) return;

    // ---- epilogue: dice + output + state reset ----
    __shared__ float dice[MAXN][NCLS];
    __shared__ float mean_c[NCLS];
    __shared__ float total_s;
    if (tid < N * NCLS) {
        int nn = tid / NCLS, c = tid % NCLS;
        float inter = (float)g_cnt[nn][2 * NCLS + c];
        float sums = (float)(g_cnt[nn][0 * NCLS + c] + g_cnt[nn][1 * NCLS + c]);
        dice[nn][c] = (2.0f * inter + 1e-5f) / (sums + 1e-5f);
    }
    __syncthreads();
    if (tid < NCLS) {
        float m = 0.0f;
        for (int i = 0; i < N; i++) m += dice[i][tid];
        mean_c[tid] = m / (float)N;
    }
    __syncthreads();
    if (tid == 0) {
        float t = 0.0f;
#pragma unroll
        for (int c = 0; c < NCLS; c++) t += w[c] * mean_c[c];
        total_s = t;
    }
    __syncthreads();

    for (int i = tid; i < out_size; i += 256) {
        float v;
        if (out_size >= NCLS + 1) {
            v = (i == 0) ? total_s : (i <= NCLS ? mean_c[i - 1] : 0.0f);
        } else if (out_size == NCLS) {
            v = mean_c[i];
        } else {
            v = (i == 0) ? total_s : (i - 1 < NCLS ? mean_c[i - 1] : 0.0f);
        }
        out[i] = v;
    }

    // reset for next graph replay (kernel boundary publishes these)
    if (tid < MAXN * NSLOT) ((int*)g_cnt)[tid] = 0;
    if (tid == 0) g_done = 0u;
}

extern "C" void kernel_launch(void* const* d_in, const int* in_sizes, int n_in,
                              void* d_out, int out_size) {
    const int* inB = (const int*)d_in[0];
    const int* tgB = (const int*)d_in[1];
    const float* w = (const float*)d_in[2];
    float* out = (float*)d_out;

    int N = in_sizes[0] / PIX;
    if (N < 1) N = 1;
    if (N > MAXN) N = MAXN;

    dim3 grid(GX, N);
    k_dice_fused<<<grid, 256>>>(inB, tgB, w, out, out_size, N);
}